// round 14
// baseline (speedup 1.0000x reference)
#include <cuda_runtime.h>
#include <cstdint>

#define BB    64
#define CIN   64
#define HH    56
#define WW    56
#define CHN   512
#define IN_DIM (CIN*HH*WW)      // 200704
#define NKEEP 128
#define SPLITK 112
#define KC (IN_DIM/SPLITK)      // 1792
#define SPAT (HH*WW)            // 3136
#define NTILES 25               // ceil(3136/128)
#define ASTRIDE 36              // router padded row stride (floats)
#define RKCH (KC/32)            // 56 router k-chunks per split
#define RSTAGE ((64+128)*ASTRIDE)   // router stage floats (6912)

#define CKCH 36                 // conv chunks: 9 taps * 4 ci-quarters of 16
#define CSTRIDE 24              // conv padded row stride (floats), LDS.64-safe
#define CSTAGEF (256*CSTRIDE)   // conv stage floats (6144)

// ---------------- small helpers ----------------
__device__ __forceinline__ float to_tf32(float f) {
    uint32_t u; asm("cvt.rna.tf32.f32 %0, %1;" : "=r"(u) : "f"(f));
    return __uint_as_float(u);
}
__device__ __forceinline__ void mma_tf32(float* c, const uint32_t* a, const uint32_t* b) {
    asm volatile(
        "mma.sync.aligned.m16n8k8.row.col.f32.tf32.tf32.f32 "
        "{%0,%1,%2,%3}, {%4,%5,%6,%7}, {%8,%9}, {%0,%1,%2,%3};"
        : "+f"(c[0]), "+f"(c[1]), "+f"(c[2]), "+f"(c[3])
        : "r"(a[0]), "r"(a[1]), "r"(a[2]), "r"(a[3]), "r"(b[0]), "r"(b[1]));
}
__device__ __forceinline__ void cp16(uint32_t dst_smem, const void* src, uint32_t srcsz) {
    asm volatile("cp.async.cg.shared.global [%0], [%1], 16, %2;"
                 :: "r"(dst_smem), "l"(src), "r"(srcsz));
}
#define CP_COMMIT() asm volatile("cp.async.commit_group;" ::: "memory")
#define CP_WAIT(n)  asm volatile("cp.async.wait_group %0;" :: "n"(n) : "memory")

// exact hi/lo split: hi is exactly tf32-representable, lo = v - hi exactly.
__device__ __forceinline__ void split_tf32(float v, uint32_t& hi, uint32_t& lo) {
    uint32_t u = __float_as_uint(v) & 0xFFFFE000u;
    hi = u;
    lo = __float_as_uint(v - __uint_as_float(u));
}

// ---------------- scratch ----------------
__device__ float g_partial[SPLITK * BB * CHN];  // 14.7 MB
__device__ int   g_idx[BB * NKEEP];
__device__ float g_xt[(size_t)BB * SPAT * CIN];   // x channels-last, tf32-rounded
__device__ float g_cwt[CHN * 576];                // cw reordered [c][tap*64+ci], tf32 (1.2MB)

// ---------------------------------------------------------------------------
// Kernel T (idx 0): transpose x to channels-last, rounding to tf32.
// ---------------------------------------------------------------------------
__global__ __launch_bounds__(256) void transpose_x(const float* __restrict__ x) {
    __shared__ float tile[32][33];
    const int s0 = blockIdx.x * 32;
    const int c0 = blockIdx.y * 32;
    const int b  = blockIdx.z;
    const int tx = threadIdx.x;
    const int ty = threadIdx.y;
#pragma unroll
    for (int k = 0; k < 4; k++) {
        int ci = c0 + ty + k * 8;
        tile[ty + k * 8][tx] = x[((size_t)b * CIN + ci) * SPAT + s0 + tx];
    }
    __syncthreads();
#pragma unroll
    for (int k = 0; k < 4; k++) {
        int srow = s0 + ty + k * 8;
        g_xt[((size_t)b * SPAT + srow) * CIN + c0 + tx] = to_tf32(tile[tx][ty + k * 8]);
    }
}

// ---------------------------------------------------------------------------
// Kernel 1 (idx 1): router GEMM partials on tensor cores, tf32x3.
// PROVEN R9/R10/R13 config: scalar-LDS fragments, ASTRIDE 36, 3-stage
// cp.async (wait_group 1), SPLITK=112. Block M=64 x N=128, 8 warps (2m x 4n).
// ---------------------------------------------------------------------------
__global__ __launch_bounds__(256) void router_tc(const float* __restrict__ x,
                                                 const float* __restrict__ rw) {
    extern __shared__ float rs[];   // [3][RSTAGE]

    const int ntile = blockIdx.x;    // 0..3
    const int sk    = blockIdx.y;    // 0..111
    const int tid  = threadIdx.x;
    const int lane = tid & 31;
    const int wid  = tid >> 5;
    const int wm   = wid & 1;
    const int wn   = wid >> 1;

    const int ar = tid >> 2, aq = tid & 3;
    const int br = tid >> 1, bh2 = tid & 1;
    const float* asrc0 = x  + (size_t)ar * IN_DIM + (size_t)sk * KC + aq * 8;
    const float* bsrc0 = rw + (size_t)(ntile * 128 + br) * IN_DIM + (size_t)sk * KC + bh2 * 16;
    const uint32_t base = (uint32_t)__cvta_generic_to_shared(rs);
    const uint32_t dstA = base + (ar * ASTRIDE + aq * 8) * 4;
    const uint32_t dstB = base + (64 * ASTRIDE + br * ASTRIDE + bh2 * 16) * 4;
    const uint32_t stageBytes = RSTAGE * 4;

    auto issue = [&](int kc, int p) {
        if (kc < RKCH) {
            const int k0 = kc * 32;
            const uint32_t dA = dstA + p * stageBytes;
            const uint32_t dB = dstB + p * stageBytes;
            cp16(dA,      asrc0 + k0,      16u);
            cp16(dA + 16, asrc0 + k0 + 4,  16u);
#pragma unroll
            for (int j = 0; j < 4; j++) cp16(dB + j * 16, bsrc0 + k0 + j * 4, 16u);
        }
        CP_COMMIT();   // empty group at tail keeps wait-count invariant
    };

    float acc[2][4][4];
#pragma unroll
    for (int mt = 0; mt < 2; mt++)
#pragma unroll
        for (int nt = 0; nt < 4; nt++)
#pragma unroll
            for (int c = 0; c < 4; c++) acc[mt][nt][c] = 0.f;

    const int lr = lane >> 2;
    const int lc = lane & 3;
    const int aRow0 = wm * 32 + lr;
    const int bRow0 = wn * 32 + lr;

    issue(0, 0);
    issue(1, 1);

    int ps = 0, pn = 2;
#pragma unroll 1
    for (int kc = 0; kc < RKCH; kc++) {
        CP_WAIT(1);
        __syncthreads();
        issue(kc + 2, pn);

        const float* A = rs + ps * RSTAGE;
        const float* B = rs + ps * RSTAGE + 64 * ASTRIDE;
#pragma unroll
        for (int k8 = 0; k8 < 4; k8++) {
            const int k0 = k8 * 8 + lc;
            uint32_t ah[2][4], al[2][4];
#pragma unroll
            for (int mt = 0; mt < 2; mt++) {
                const float* ap = A + (aRow0 + mt * 16) * ASTRIDE + k0;
                split_tf32(ap[0],               ah[mt][0], al[mt][0]);
                split_tf32(ap[8 * ASTRIDE],     ah[mt][1], al[mt][1]);
                split_tf32(ap[4],               ah[mt][2], al[mt][2]);
                split_tf32(ap[8 * ASTRIDE + 4], ah[mt][3], al[mt][3]);
            }
            uint32_t bh[4][2], bl[4][2];
#pragma unroll
            for (int nt = 0; nt < 4; nt++) {
                const float* bp = B + (bRow0 + nt * 8) * ASTRIDE + k0;
                split_tf32(bp[0], bh[nt][0], bl[nt][0]);
                split_tf32(bp[4], bh[nt][1], bl[nt][1]);
            }
#pragma unroll
            for (int mt = 0; mt < 2; mt++)
#pragma unroll
                for (int nt = 0; nt < 4; nt++) {
                    mma_tf32(acc[mt][nt], al[mt], bh[nt]);
                    mma_tf32(acc[mt][nt], ah[mt], bl[nt]);
                    mma_tf32(acc[mt][nt], ah[mt], bh[nt]);
                }
        }
        ps = (ps == 2) ? 0 : ps + 1;
        pn = (pn == 2) ? 0 : pn + 1;
    }

    const int row0 = lane >> 2;
    const int col0 = (lane & 3) * 2;
#pragma unroll
    for (int mt = 0; mt < 2; mt++) {
#pragma unroll
        for (int nt = 0; nt < 4; nt++) {
            int m = wm * 32 + mt * 16 + row0;
            int n = ntile * 128 + wn * 32 + nt * 8 + col0;
            float* p0 = &g_partial[((size_t)sk * BB + m) * CHN + n];
            p0[0] = acc[mt][nt][0];
            p0[1] = acc[mt][nt][1];
            float* p1 = p0 + 8 * CHN;
            p1[0] = acc[mt][nt][2];
            p1[1] = acc[mt][nt][3];
        }
    }
}

// ---------------------------------------------------------------------------
// Kernel 2 (idx 2): FUSED reduce + stable top-128 + cwt reorder.
// Gather of per-sample weights ELIMINATED: instead block m reorders channels
// 8m..8m+7 of cw into g_cwt (coalesced, 1.2MB total); conv reads g_cwt
// directly via g_idx indirection.
// ---------------------------------------------------------------------------
__global__ __launch_bounds__(CHN) void fuse_select(const float* __restrict__ rb,
                                                   const float* __restrict__ cw) {
    __shared__ float sa[CHN];
    __shared__ unsigned char keep[CHN];
    const int m = blockIdx.x;
    const int i = threadIdx.x;

    float sum = rb[i];
#pragma unroll 8
    for (int s = 0; s < SPLITK; s++)
        sum += g_partial[((size_t)s * BB + m) * CHN + i];

    float v = fabsf(sum);
    sa[i] = v;
    __syncthreads();
    int rank = 0;
    for (int j = 0; j < CHN; j++) {
        float u = sa[j];
        rank += (u > v) || (u == v && j < i);
    }
    keep[i] = (rank < NKEEP) ? 1 : 0;
    __syncthreads();
    if (keep[i]) {
        int pos = 0;
        for (int j = 0; j < i; j++) pos += keep[j];
        g_idx[m * NKEEP + pos] = i;
    }

    // reorder + tf32-round this block's slice of cw: channels 8m..8m+7
    // g_cwt[c][tap*64+ci] = tf32(cw[c][ci*9+tap]); writes coalesced.
    for (int t = i; t < 8 * 576; t += CHN) {
        int cc = (m * 8) + (t / 576);
        int kk = t % 576;
        g_cwt[cc * 576 + kk] = to_tf32(cw[(size_t)cc * 576 + (kk & 63) * 9 + (kk >> 6)]);
    }
}

// ---------------------------------------------------------------------------
// Kernel 4 (idx 3, profiled): conv implicit GEMM, tf32 m16n8k8.
// PROVEN R11 mainloop: 4-stage cp.async, K=16 chunks, LDS.64 k-permuted
// fragments. B now staged directly from L2-resident g_cwt via g_idx.
// ---------------------------------------------------------------------------
__global__ __launch_bounds__(256, 2) void conv_mma(const float* __restrict__ cb,
                                                   float* __restrict__ out) {
    extern __shared__ float dyn[];   // [4][CSTAGEF]
    __shared__ float sbias[NKEEP];

    const int tid  = threadIdx.x;
    const int lane = tid & 31;
    const int wid  = tid >> 5;
    const int wm   = wid & 1;
    const int wn   = wid >> 1;
    const int t = blockIdx.x;
    const int b = blockIdx.y;

    if (tid < NKEEP) sbias[tid] = cb[g_idx[b * NKEEP + tid]];

    const int r = tid >> 1;
    const int h = tid & 1;
    const int s_st = t * 128 + r;
    const int hh = s_st / WW;
    const int ww = s_st % WW;
    const int csel = g_idx[b * NKEEP + r];      // selected channel for B row r
    const float* bsrc0 = g_cwt + (size_t)csel * 576 + h * 8;
    const float* abase = g_xt + (((size_t)b * SPAT) << 6) + h * 8;

    uint32_t smem_base = (uint32_t)__cvta_generic_to_shared(dyn);
    const uint32_t dstA0 = smem_base + (r * CSTRIDE + h * 8) * 4;
    const uint32_t dstB0 = smem_base + (128 * CSTRIDE + r * CSTRIDE + h * 8) * 4;
    const uint32_t stageB = CSTAGEF * 4;

    auto issue_chunk = [&](int kc, int p) {
        if (kc < CKCH) {
            const int tap = kc >> 2;
            const int q   = kc & 3;
            const int hp = hh + tap / 3 - 1;
            const int wp = ww + tap % 3 - 1;
            const bool valid = (s_st < SPAT) && ((unsigned)hp < (unsigned)HH) &&
                               ((unsigned)wp < (unsigned)WW);
            const uint32_t sz = valid ? 16u : 0u;
            int off = valid ? (hp * WW + wp) : 0;
            const float* asrc = abase + (((size_t)off) << 6) + q * 16;
            const float* bsrc = bsrc0 + kc * 16;
            const uint32_t dA = dstA0 + p * stageB;
            const uint32_t dB = dstB0 + p * stageB;
            cp16(dA,      asrc,     sz);
            cp16(dA + 16, asrc + 4, sz);
            cp16(dB,      bsrc,     16u);
            cp16(dB + 16, bsrc + 4, 16u);
        }
        CP_COMMIT();
    };

    float acc[4][4][4];
#pragma unroll
    for (int mt = 0; mt < 4; mt++)
#pragma unroll
        for (int nt = 0; nt < 4; nt++)
#pragma unroll
            for (int c = 0; c < 4; c++) acc[mt][nt][c] = 0.f;

    const int lr = lane >> 2;
    const int lc = lane & 3;
    const int aRow0 = wm * 64 + lr;
    const int bRow0 = wn * 32 + lr;

    issue_chunk(0, 0);
    issue_chunk(1, 1);
    issue_chunk(2, 2);

#pragma unroll 1
    for (int kc = 0; kc < CKCH; kc++) {
        const int p = kc & 3;
        CP_WAIT(2);
        __syncthreads();
        issue_chunk(kc + 3, (kc + 3) & 3);

        const float* A = dyn + p * CSTAGEF;
        const float* B = dyn + p * CSTAGEF + 128 * CSTRIDE;
#pragma unroll
        for (int k8 = 0; k8 < 2; k8++) {
            const int k0 = k8 * 8 + 2 * lc;     // logical (2lc, 2lc+1) pair
            uint32_t af[4][4];
#pragma unroll
            for (int mt = 0; mt < 4; mt++) {
                const float* ap = A + (aRow0 + mt * 16) * CSTRIDE + k0;
                float2 v0 = *(const float2*)ap;
                float2 v1 = *(const float2*)(ap + 8 * CSTRIDE);
                af[mt][0] = __float_as_uint(v0.x);
                af[mt][1] = __float_as_uint(v1.x);
                af[mt][2] = __float_as_uint(v0.y);
                af[mt][3] = __float_as_uint(v1.y);
            }
            uint32_t bf[4][2];
#pragma unroll
            for (int nt = 0; nt < 4; nt++) {
                float2 v = *(const float2*)(B + (bRow0 + nt * 8) * CSTRIDE + k0);
                bf[nt][0] = __float_as_uint(v.x);
                bf[nt][1] = __float_as_uint(v.y);
            }
#pragma unroll
            for (int mt = 0; mt < 4; mt++)
#pragma unroll
                for (int nt = 0; nt < 4; nt++)
                    mma_tf32(acc[mt][nt], af[mt], bf[nt]);
        }
    }

    const int row0 = lane >> 2;
    const int col0 = (lane & 3) * 2;
#pragma unroll
    for (int mt = 0; mt < 4; mt++) {
#pragma unroll
        for (int nt = 0; nt < 4; nt++) {
            int n  = wn * 32 + nt * 8 + col0;
            int sr = t * 128 + wm * 64 + mt * 16 + row0;
            float b0 = sbias[n], b1 = sbias[n + 1];
            float* op0 = out + ((size_t)b * NKEEP + n) * SPAT;
            float* op1 = op0 + SPAT;
            if (sr < SPAT) {
                op0[sr] = acc[mt][nt][0] + b0;
                op1[sr] = acc[mt][nt][1] + b1;
            }
            if (sr + 8 < SPAT) {
                op0[sr + 8] = acc[mt][nt][2] + b0;
                op1[sr + 8] = acc[mt][nt][3] + b1;
            }
        }
    }
}

// ---------------------------------------------------------------------------
extern "C" void kernel_launch(void* const* d_in, const int* in_sizes, int n_in,
                              void* d_out, int out_size) {
    const float* x  = (const float*)d_in[0];   // [64,64,56,56]
    const float* cw = (const float*)d_in[1];   // [512,64,3,3]
    const float* cb = (const float*)d_in[2];   // [512]
    const float* rw = (const float*)d_in[3];   // [512,200704]
    const float* rb = (const float*)d_in[4];   // [512]
    float* out = (float*)d_out;                // [64,128,56,56]

    const int convsmem = 4 * CSTAGEF * 4;      // 98304 bytes
    const int rtsmem   = 3 * RSTAGE * 4;       // 82944 bytes
    cudaFuncSetAttribute(conv_mma, cudaFuncAttributeMaxDynamicSharedMemorySize, convsmem);
    cudaFuncSetAttribute(router_tc, cudaFuncAttributeMaxDynamicSharedMemorySize, rtsmem);

    transpose_x<<<dim3(SPAT / 32, CIN / 32, BB), dim3(32, 8)>>>(x);  // idx 0
    router_tc<<<dim3(CHN / 128, SPLITK), 256, rtsmem>>>(x, rw);       // idx 1
    fuse_select<<<BB, CHN>>>(rb, cw);                                 // idx 2
    conv_mma<<<dim3(NTILES, BB), 256, convsmem>>>(cb, out);           // idx 3 (profiled)
}

// round 15
// speedup vs baseline: 1.5344x; 1.5344x over previous
#include <cuda_runtime.h>
#include <cstdint>

#define BB    64
#define CIN   64
#define HH    56
#define WW    56
#define CHN   512
#define IN_DIM (CIN*HH*WW)      // 200704
#define NKEEP 128
#define SPLITK 112
#define KC (IN_DIM/SPLITK)      // 1792
#define SPAT (HH*WW)            // 3136
#define NTILES 25               // ceil(3136/128)
#define ASTRIDE 36              // router padded row stride (floats)
#define RKCH (KC/32)            // 56 router k-chunks per split
#define RSTAGE ((64+128)*ASTRIDE)   // router stage floats (6912)

#define CKCH 36                 // conv chunks: 9 taps * 4 ci-quarters of 16
#define CSTRIDE 24              // conv padded row stride (floats), LDS.64-safe
#define CSTAGEF (256*CSTRIDE)   // conv stage floats (6144)

// ---------------- small helpers ----------------
__device__ __forceinline__ float to_tf32(float f) {
    uint32_t u; asm("cvt.rna.tf32.f32 %0, %1;" : "=r"(u) : "f"(f));
    return __uint_as_float(u);
}
__device__ __forceinline__ void mma_tf32(float* c, const uint32_t* a, const uint32_t* b) {
    asm volatile(
        "mma.sync.aligned.m16n8k8.row.col.f32.tf32.tf32.f32 "
        "{%0,%1,%2,%3}, {%4,%5,%6,%7}, {%8,%9}, {%0,%1,%2,%3};"
        : "+f"(c[0]), "+f"(c[1]), "+f"(c[2]), "+f"(c[3])
        : "r"(a[0]), "r"(a[1]), "r"(a[2]), "r"(a[3]), "r"(b[0]), "r"(b[1]));
}
__device__ __forceinline__ void cp16(uint32_t dst_smem, const void* src, uint32_t srcsz) {
    asm volatile("cp.async.cg.shared.global [%0], [%1], 16, %2;"
                 :: "r"(dst_smem), "l"(src), "r"(srcsz));
}
#define CP_COMMIT() asm volatile("cp.async.commit_group;" ::: "memory")
#define CP_WAIT(n)  asm volatile("cp.async.wait_group %0;" :: "n"(n) : "memory")

// exact hi/lo split: hi is exactly tf32-representable, lo = v - hi exactly.
__device__ __forceinline__ void split_tf32(float v, uint32_t& hi, uint32_t& lo) {
    uint32_t u = __float_as_uint(v) & 0xFFFFE000u;
    hi = u;
    lo = __float_as_uint(v - __uint_as_float(u));
}

// ---------------- scratch ----------------
__device__ float g_partial[SPLITK * BB * CHN];  // 14.7 MB
__device__ int   g_idx[BB * NKEEP];
__device__ float g_xt[(size_t)BB * SPAT * CIN];   // x channels-last, tf32-rounded
__device__ float g_cwt[CHN * 576];                // cw reordered [c][tap*64+ci], tf32 (1.2MB)

// ---------------------------------------------------------------------------
// Kernel T (idx 0): transpose x to channels-last, rounding to tf32.
// ---------------------------------------------------------------------------
__global__ __launch_bounds__(256) void transpose_x(const float* __restrict__ x) {
    __shared__ float tile[32][33];
    const int s0 = blockIdx.x * 32;
    const int c0 = blockIdx.y * 32;
    const int b  = blockIdx.z;
    const int tx = threadIdx.x;
    const int ty = threadIdx.y;
#pragma unroll
    for (int k = 0; k < 4; k++) {
        int ci = c0 + ty + k * 8;
        tile[ty + k * 8][tx] = x[((size_t)b * CIN + ci) * SPAT + s0 + tx];
    }
    __syncthreads();
#pragma unroll
    for (int k = 0; k < 4; k++) {
        int srow = s0 + ty + k * 8;
        g_xt[((size_t)b * SPAT + srow) * CIN + c0 + tx] = to_tf32(tile[tx][ty + k * 8]);
    }
}

// ---------------------------------------------------------------------------
// Kernel 1 (idx 1): router GEMM partials on tensor cores, tf32x3.
// PROVEN config: scalar-LDS fragments, ASTRIDE 36, 3-stage cp.async
// (wait_group 1), SPLITK=112. Block M=64 x N=128, 8 warps (2m x 4n).
// ---------------------------------------------------------------------------
__global__ __launch_bounds__(256) void router_tc(const float* __restrict__ x,
                                                 const float* __restrict__ rw) {
    extern __shared__ float rs[];   // [3][RSTAGE]

    const int ntile = blockIdx.x;    // 0..3
    const int sk    = blockIdx.y;    // 0..111
    const int tid  = threadIdx.x;
    const int lane = tid & 31;
    const int wid  = tid >> 5;
    const int wm   = wid & 1;
    const int wn   = wid >> 1;

    const int ar = tid >> 2, aq = tid & 3;
    const int br = tid >> 1, bh2 = tid & 1;
    const float* asrc0 = x  + (size_t)ar * IN_DIM + (size_t)sk * KC + aq * 8;
    const float* bsrc0 = rw + (size_t)(ntile * 128 + br) * IN_DIM + (size_t)sk * KC + bh2 * 16;
    const uint32_t base = (uint32_t)__cvta_generic_to_shared(rs);
    const uint32_t dstA = base + (ar * ASTRIDE + aq * 8) * 4;
    const uint32_t dstB = base + (64 * ASTRIDE + br * ASTRIDE + bh2 * 16) * 4;
    const uint32_t stageBytes = RSTAGE * 4;

    auto issue = [&](int kc, int p) {
        if (kc < RKCH) {
            const int k0 = kc * 32;
            const uint32_t dA = dstA + p * stageBytes;
            const uint32_t dB = dstB + p * stageBytes;
            cp16(dA,      asrc0 + k0,      16u);
            cp16(dA + 16, asrc0 + k0 + 4,  16u);
#pragma unroll
            for (int j = 0; j < 4; j++) cp16(dB + j * 16, bsrc0 + k0 + j * 4, 16u);
        }
        CP_COMMIT();   // empty group at tail keeps wait-count invariant
    };

    float acc[2][4][4];
#pragma unroll
    for (int mt = 0; mt < 2; mt++)
#pragma unroll
        for (int nt = 0; nt < 4; nt++)
#pragma unroll
            for (int c = 0; c < 4; c++) acc[mt][nt][c] = 0.f;

    const int lr = lane >> 2;
    const int lc = lane & 3;
    const int aRow0 = wm * 32 + lr;
    const int bRow0 = wn * 32 + lr;

    issue(0, 0);
    issue(1, 1);

    int ps = 0, pn = 2;
#pragma unroll 1
    for (int kc = 0; kc < RKCH; kc++) {
        CP_WAIT(1);
        __syncthreads();
        issue(kc + 2, pn);

        const float* A = rs + ps * RSTAGE;
        const float* B = rs + ps * RSTAGE + 64 * ASTRIDE;
#pragma unroll
        for (int k8 = 0; k8 < 4; k8++) {
            const int k0 = k8 * 8 + lc;
            uint32_t ah[2][4], al[2][4];
#pragma unroll
            for (int mt = 0; mt < 2; mt++) {
                const float* ap = A + (aRow0 + mt * 16) * ASTRIDE + k0;
                split_tf32(ap[0],               ah[mt][0], al[mt][0]);
                split_tf32(ap[8 * ASTRIDE],     ah[mt][1], al[mt][1]);
                split_tf32(ap[4],               ah[mt][2], al[mt][2]);
                split_tf32(ap[8 * ASTRIDE + 4], ah[mt][3], al[mt][3]);
            }
            uint32_t bh[4][2], bl[4][2];
#pragma unroll
            for (int nt = 0; nt < 4; nt++) {
                const float* bp = B + (bRow0 + nt * 8) * ASTRIDE + k0;
                split_tf32(bp[0], bh[nt][0], bl[nt][0]);
                split_tf32(bp[4], bh[nt][1], bl[nt][1]);
            }
#pragma unroll
            for (int mt = 0; mt < 2; mt++)
#pragma unroll
                for (int nt = 0; nt < 4; nt++) {
                    mma_tf32(acc[mt][nt], al[mt], bh[nt]);
                    mma_tf32(acc[mt][nt], ah[mt], bl[nt]);
                    mma_tf32(acc[mt][nt], ah[mt], bh[nt]);
                }
        }
        ps = (ps == 2) ? 0 : ps + 1;
        pn = (pn == 2) ? 0 : pn + 1;
    }

    const int row0 = lane >> 2;
    const int col0 = (lane & 3) * 2;
#pragma unroll
    for (int mt = 0; mt < 2; mt++) {
#pragma unroll
        for (int nt = 0; nt < 4; nt++) {
            int m = wm * 32 + mt * 16 + row0;
            int n = ntile * 128 + wn * 32 + nt * 8 + col0;
            float* p0 = &g_partial[((size_t)sk * BB + m) * CHN + n];
            p0[0] = acc[mt][nt][0];
            p0[1] = acc[mt][nt][1];
            float* p1 = p0 + 8 * CHN;
            p1[0] = acc[mt][nt][2];
            p1[1] = acc[mt][nt][3];
        }
    }
}

// ---------------------------------------------------------------------------
// Kernel 2 (idx 2): FUSED reduce + stable top-128 + cwt reorder.
// ---------------------------------------------------------------------------
__global__ __launch_bounds__(CHN) void fuse_select(const float* __restrict__ rb,
                                                   const float* __restrict__ cw) {
    __shared__ float sa[CHN];
    __shared__ unsigned char keep[CHN];
    const int m = blockIdx.x;
    const int i = threadIdx.x;

    float sum = rb[i];
#pragma unroll 8
    for (int s = 0; s < SPLITK; s++)
        sum += g_partial[((size_t)s * BB + m) * CHN + i];

    float v = fabsf(sum);
    sa[i] = v;
    __syncthreads();
    int rank = 0;
    for (int j = 0; j < CHN; j++) {
        float u = sa[j];
        rank += (u > v) || (u == v && j < i);
    }
    keep[i] = (rank < NKEEP) ? 1 : 0;
    __syncthreads();
    if (keep[i]) {
        int pos = 0;
        for (int j = 0; j < i; j++) pos += keep[j];
        g_idx[m * NKEEP + pos] = i;
    }

    // reorder + tf32-round this block's slice of cw: channels 8m..8m+7
    for (int t = i; t < 8 * 576; t += CHN) {
        int cc = (m * 8) + (t / 576);
        int kk = t % 576;
        g_cwt[cc * 576 + kk] = to_tf32(cw[(size_t)cc * 576 + (kk & 63) * 9 + (kk >> 6)]);
    }
}

// ---------------------------------------------------------------------------
// Kernel 4 (idx 3, profiled): conv implicit GEMM, tf32 m16n8k8.
// PROVEN R11 mainloop: 4-stage cp.async, K=16 chunks, LDS.64 k-permuted
// fragments. B staged from L2-resident g_cwt via g_idx.
// ---------------------------------------------------------------------------
__global__ __launch_bounds__(256, 2) void conv_mma(const float* __restrict__ cb,
                                                   float* __restrict__ out) {
    extern __shared__ float dyn[];   // [4][CSTAGEF]
    __shared__ float sbias[NKEEP];

    const int tid  = threadIdx.x;
    const int lane = tid & 31;
    const int wid  = tid >> 5;
    const int wm   = wid & 1;
    const int wn   = wid >> 1;
    const int t = blockIdx.x;
    const int b = blockIdx.y;

    if (tid < NKEEP) sbias[tid] = cb[g_idx[b * NKEEP + tid]];

    const int r = tid >> 1;
    const int h = tid & 1;
    const int s_st = t * 128 + r;
    const int hh = s_st / WW;
    const int ww = s_st % WW;
    const int csel = g_idx[b * NKEEP + r];      // selected channel for B row r
    const float* bsrc0 = g_cwt + (size_t)csel * 576 + h * 8;
    const float* abase = g_xt + (((size_t)b * SPAT) << 6) + h * 8;

    uint32_t smem_base = (uint32_t)__cvta_generic_to_shared(dyn);
    const uint32_t dstA0 = smem_base + (r * CSTRIDE + h * 8) * 4;
    const uint32_t dstB0 = smem_base + (128 * CSTRIDE + r * CSTRIDE + h * 8) * 4;
    const uint32_t stageB = CSTAGEF * 4;

    auto issue_chunk = [&](int kc, int p) {
        if (kc < CKCH) {
            const int tap = kc >> 2;
            const int q   = kc & 3;
            const int hp = hh + tap / 3 - 1;
            const int wp = ww + tap % 3 - 1;
            const bool valid = (s_st < SPAT) && ((unsigned)hp < (unsigned)HH) &&
                               ((unsigned)wp < (unsigned)WW);
            const uint32_t sz = valid ? 16u : 0u;
            int off = valid ? (hp * WW + wp) : 0;
            const float* asrc = abase + (((size_t)off) << 6) + q * 16;
            const float* bsrc = bsrc0 + kc * 16;
            const uint32_t dA = dstA0 + p * stageB;
            const uint32_t dB = dstB0 + p * stageB;
            cp16(dA,      asrc,     sz);
            cp16(dA + 16, asrc + 4, sz);
            cp16(dB,      bsrc,     16u);
            cp16(dB + 16, bsrc + 4, 16u);
        }
        CP_COMMIT();
    };

    float acc[4][4][4];
#pragma unroll
    for (int mt = 0; mt < 4; mt++)
#pragma unroll
        for (int nt = 0; nt < 4; nt++)
#pragma unroll
            for (int c = 0; c < 4; c++) acc[mt][nt][c] = 0.f;

    const int lr = lane >> 2;
    const int lc = lane & 3;
    const int aRow0 = wm * 64 + lr;
    const int bRow0 = wn * 32 + lr;

    issue_chunk(0, 0);
    issue_chunk(1, 1);
    issue_chunk(2, 2);

#pragma unroll 1
    for (int kc = 0; kc < CKCH; kc++) {
        const int p = kc & 3;
        CP_WAIT(2);
        __syncthreads();
        issue_chunk(kc + 3, (kc + 3) & 3);

        const float* A = dyn + p * CSTAGEF;
        const float* B = dyn + p * CSTAGEF + 128 * CSTRIDE;
#pragma unroll
        for (int k8 = 0; k8 < 2; k8++) {
            const int k0 = k8 * 8 + 2 * lc;     // logical (2lc, 2lc+1) pair
            uint32_t af[4][4];
#pragma unroll
            for (int mt = 0; mt < 4; mt++) {
                const float* ap = A + (aRow0 + mt * 16) * CSTRIDE + k0;
                float2 v0 = *(const float2*)ap;
                float2 v1 = *(const float2*)(ap + 8 * CSTRIDE);
                af[mt][0] = __float_as_uint(v0.x);
                af[mt][1] = __float_as_uint(v1.x);
                af[mt][2] = __float_as_uint(v0.y);
                af[mt][3] = __float_as_uint(v1.y);
            }
            uint32_t bf[4][2];
#pragma unroll
            for (int nt = 0; nt < 4; nt++) {
                float2 v = *(const float2*)(B + (bRow0 + nt * 8) * CSTRIDE + k0);
                bf[nt][0] = __float_as_uint(v.x);
                bf[nt][1] = __float_as_uint(v.y);
            }
#pragma unroll
            for (int mt = 0; mt < 4; mt++)
#pragma unroll
                for (int nt = 0; nt < 4; nt++)
                    mma_tf32(acc[mt][nt], af[mt], bf[nt]);
        }
    }

    const int row0 = lane >> 2;
    const int col0 = (lane & 3) * 2;
#pragma unroll
    for (int mt = 0; mt < 4; mt++) {
#pragma unroll
        for (int nt = 0; nt < 4; nt++) {
            int n  = wn * 32 + nt * 8 + col0;
            int sr = t * 128 + wm * 64 + mt * 16 + row0;
            float b0 = sbias[n], b1 = sbias[n + 1];
            float* op0 = out + ((size_t)b * NKEEP + n) * SPAT;
            float* op1 = op0 + SPAT;
            if (sr < SPAT) {
                op0[sr] = acc[mt][nt][0] + b0;
                op1[sr] = acc[mt][nt][1] + b1;
            }
            if (sr + 8 < SPAT) {
                op0[sr + 8] = acc[mt][nt][2] + b0;
                op1[sr + 8] = acc[mt][nt][3] + b1;
            }
        }
    }
}

// ---------------------------------------------------------------------------
extern "C" void kernel_launch(void* const* d_in, const int* in_sizes, int n_in,
                              void* d_out, int out_size) {
    const float* x  = (const float*)d_in[0];   // [64,64,56,56]
    const float* cw = (const float*)d_in[1];   // [512,64,3,3]
    const float* cb = (const float*)d_in[2];   // [512]
    const float* rw = (const float*)d_in[3];   // [512,200704]
    const float* rb = (const float*)d_in[4];   // [512]
    float* out = (float*)d_out;                // [64,128,56,56]

    const int convsmem = 4 * CSTAGEF * 4;      // 98304 bytes
    const int rtsmem   = 3 * RSTAGE * 4;       // 82944 bytes
    cudaFuncSetAttribute(conv_mma, cudaFuncAttributeMaxDynamicSharedMemorySize, convsmem);
    cudaFuncSetAttribute(router_tc, cudaFuncAttributeMaxDynamicSharedMemorySize, rtsmem);

    transpose_x<<<dim3(SPAT / 32, CIN / 32, BB), dim3(32, 8)>>>(x);  // idx 0
    router_tc<<<dim3(CHN / 128, SPLITK), 256, rtsmem>>>(x, rw);       // idx 1
    fuse_select<<<BB, CHN>>>(rb, cw);                                 // idx 2
    conv_mma<<<dim3(NTILES, BB), 256, convsmem>>>(cb, out);           // idx 3 (profiled)
}